// round 13
// baseline (speedup 1.0000x reference)
#include <cuda_runtime.h>
#include <cuda_bf16.h>
#include <cstdint>

// Problem constants
#define NB 16
#define SS 4096
#define NTOK (NB*SS)        // 65536
#define EE 128
#define DM 64
#define NH 8
#define DH 8
#define FFD 256
#define CC 1623
#define NL 8
#define SPLIT 8

// Scratch (device globals — allocation-free per harness rules)
__device__ float g_hh[NTOK*DM];
__device__ float g_pq[NTOK*DM];
__device__ float g_pk[NTOK*DM];
__device__ float g_v [NTOK*DM];
__device__ float g_kvp[NB*NH*SPLIT*72];

__device__ __forceinline__ float phi_f(float x) {
    return x > 0.f ? x + 1.f : __expf(x);   // elu(x)+1
}

__device__ __forceinline__ float gelu_f(float x) {
    float x3 = x * x * x;
    return 0.5f * x * (1.f + tanhf(0.7978845608028654f * (x + 0.044715f * x3)));
}

// ===================== packed f32x2 helpers =====================
__device__ __forceinline__ uint64_t pack2(float x, float y) {
    uint64_t r; asm("mov.b64 %0, {%1, %2};" : "=l"(r) : "f"(x), "f"(y)); return r;
}
__device__ __forceinline__ void unpack2(uint64_t v, float& x, float& y) {
    asm("mov.b64 {%0, %1}, %2;" : "=f"(x), "=f"(y) : "l"(v));
}
__device__ __forceinline__ void ffma2(uint64_t& d, uint64_t a, uint64_t b) {
    asm("fma.rn.f32x2 %0, %1, %2, %3;" : "=l"(d) : "l"(a), "l"(b), "l"(d));
}

// ---- packed register-tiled GEMM fragments: A transposed in smem [k][tok] (pitch PA),
// ---- W in smem [k][col] (pitch PW). acc[i][j] holds output cols (c0+2j, c0+2j+1).
template<int K, int PA, int PW>
__device__ __forceinline__ void gemm_48p(const float* __restrict__ AT,
                                         const float* __restrict__ Ws,
                                         int r0, int c0, uint64_t (&acc)[4][4]) {
    #pragma unroll 8
    for (int k = 0; k < K; k++) {
        float4 a = *(const float4*)(AT + k*PA + r0);
        ulonglong2 w01 = *(const ulonglong2*)(Ws + k*PW + c0);
        ulonglong2 w23 = *(const ulonglong2*)(Ws + k*PW + c0 + 4);
        uint64_t av[4] = {pack2(a.x,a.x), pack2(a.y,a.y), pack2(a.z,a.z), pack2(a.w,a.w)};
        uint64_t wv[4] = {w01.x, w01.y, w23.x, w23.y};
        #pragma unroll
        for (int i = 0; i < 4; i++)
            #pragma unroll
            for (int j = 0; j < 4; j++)
                ffma2(acc[i][j], av[i], wv[j]);
    }
}

template<int K, int PA, int PW>
__device__ __forceinline__ void gemm_44p(const float* __restrict__ AT,
                                         const float* __restrict__ Ws,
                                         int r0, int c0, uint64_t (&acc)[4][2]) {
    #pragma unroll 8
    for (int k = 0; k < K; k++) {
        float4 a = *(const float4*)(AT + k*PA + r0);
        ulonglong2 w01 = *(const ulonglong2*)(Ws + k*PW + c0);
        uint64_t av[4] = {pack2(a.x,a.x), pack2(a.y,a.y), pack2(a.z,a.z), pack2(a.w,a.w)};
        #pragma unroll
        for (int i = 0; i < 4; i++) {
            ffma2(acc[i][0], av[i], w01.x);
            ffma2(acc[i][1], av[i], w01.y);
        }
    }
}

// ================= Kernel 0: embedding =================
// hh = (ex@we + be + lemb[labels]) @ w_in + b_in ; 64 tokens/block
// we staged in two 64-col halves -> smem ~101 KB -> 2 blocks/SM
__global__ __launch_bounds__(256, 2) void k_embed(
    const float* __restrict__ ex, const int* __restrict__ labels,
    const float* __restrict__ we, const float* __restrict__ be,
    const float* __restrict__ lemb, const float* __restrict__ w_in,
    const float* __restrict__ b_in)
{
    extern __shared__ float sm[];
    float* s_eT = sm;                // [128][68]  ex^T
    float* s_tT = sm + 128*68;       // [128][68]  tmp^T
    float* s_w  = sm + 2*128*68;     // [128][64] staging
    float* s_c  = s_w + 128*64;      // be(128) + b_in(64)
    const int tid = threadIdx.x;
    const int t0 = blockIdx.x * 64;
    const int rg = tid & 15, cg = tid >> 4;
    const int r0 = rg*4, c0 = cg*4;

    for (int i = tid; i < 192; i += 256)
        s_c[i] = (i < 128) ? be[i] : b_in[i-128];
    for (int i = tid; i < 64*EE; i += 256) {
        int r = i >> 7, c = i & 127;
        s_eT[c*68 + r] = ex[(size_t)(t0+r)*EE + c];
    }

    // stage A in two 64-col halves of we
    for (int h = 0; h < 2; h++) {
        __syncthreads();
        for (int i = tid; i < EE*64; i += 256) {
            int k = i >> 6, j = i & 63;
            s_w[i] = we[k*EE + h*64 + j];
        }
        __syncthreads();
        uint64_t acc[4][2];
        #pragma unroll
        for (int j = 0; j < 2; j++) { uint64_t b = pack2(s_c[h*64+c0+2*j], s_c[h*64+c0+2*j+1]);
            #pragma unroll
            for (int i = 0; i < 4; i++) acc[i][j] = b; }
        gemm_44p<EE,68,64>(s_eT, s_w, r0, c0, acc);
        #pragma unroll
        for (int i = 0; i < 4; i++) {
            int lab = labels[t0 + r0 + i];
            const float* le = lemb + (size_t)lab*EE + h*64 + c0;
            float o0,o1,o2,o3;
            unpack2(acc[i][0], o0, o1);
            unpack2(acc[i][1], o2, o3);
            s_tT[(h*64+c0+0)*68 + r0+i] = o0 + le[0];
            s_tT[(h*64+c0+1)*68 + r0+i] = o1 + le[1];
            s_tT[(h*64+c0+2)*68 + r0+i] = o2 + le[2];
            s_tT[(h*64+c0+3)*68 + r0+i] = o3 + le[3];
        }
    }
    __syncthreads();
    for (int i = tid; i < EE*DM; i += 256) s_w[i] = w_in[i];
    __syncthreads();

    // stage B: hh = tmp@w_in + b_in
    {
        uint64_t acc[4][2];
        #pragma unroll
        for (int j = 0; j < 2; j++) { uint64_t b = pack2(s_c[128+c0+2*j], s_c[128+c0+2*j+1]);
            #pragma unroll
            for (int i = 0; i < 4; i++) acc[i][j] = b; }
        gemm_44p<EE,68,64>(s_tT, s_w, r0, c0, acc);
        #pragma unroll
        for (int i = 0; i < 4; i++) {
            float o0,o1,o2,o3;
            unpack2(acc[i][0], o0, o1);
            unpack2(acc[i][1], o2, o3);
            *(float4*)(g_hh + (size_t)(t0+r0+i)*DM + c0) = make_float4(o0,o1,o2,o3);
        }
    }
}

// ================= Kernel 1: mask + LN1 + QKV (+phi) =================
// 128 tokens/block; weights staged in THREE 64-col passes -> smem ~49 KB -> 4 blocks/SM
__global__ __launch_bounds__(256, 4) void k_qkv(
    const float* __restrict__ mask,
    const float* __restrict__ ls, const float* __restrict__ lb,
    const float* __restrict__ wq, const float* __restrict__ bq,
    const float* __restrict__ wk, const float* __restrict__ bk,
    const float* __restrict__ wv, const float* __restrict__ bv)
{
    extern __shared__ float sm[];
    float* s_xT = sm;              // [64][128]
    float* s_w  = sm + 64*128;     // [64][64] staging (wq, wk, wv in turn)
    float* s_c  = s_w + 64*64;     // ls(64) lb(64) bq|bk|bv(192)
    const int tid = threadIdx.x;
    const int t0 = blockIdx.x * 128;

    for (int i = tid; i < 320; i += 256) {
        float v;
        if      (i < 64)  v = ls[i];
        else if (i < 128) v = lb[i-64];
        else if (i < 192) v = bq[i-128];
        else if (i < 256) v = bk[i-192];
        else              v = bv[i-256];
        s_c[i] = v;
    }
    // stage wq (parallel with LN register work)
    for (int i = tid; i < 64*64; i += 256) s_w[i] = wq[i];

    // LN in registers (2 threads / row, 32 cols each)
    const int r = tid >> 1, g = tid & 1;
    const int n = t0 + r;
    float m = mask[n];
    float4 vv[8];
    {
        const float4* src = (const float4*)(g_hh + (size_t)n*DM + g*32);
        #pragma unroll
        for (int q = 0; q < 8; q++) {
            float4 v = src[q];
            v.x*=m; v.y*=m; v.z*=m; v.w*=m;
            vv[q] = v;
        }
        float4* dst = (float4*)(g_hh + (size_t)n*DM + g*32);
        #pragma unroll
        for (int q = 0; q < 8; q++) dst[q] = vv[q];   // hh *= mask (residual base)
    }
    float sum = 0.f, sq = 0.f;
    #pragma unroll
    for (int q = 0; q < 8; q++) {
        sum += vv[q].x+vv[q].y+vv[q].z+vv[q].w;
        sq  += vv[q].x*vv[q].x+vv[q].y*vv[q].y+vv[q].z*vv[q].z+vv[q].w*vv[q].w;
    }
    sum += __shfl_xor_sync(0xffffffffu, sum, 1);
    sq  += __shfl_xor_sync(0xffffffffu, sq , 1);
    float mean = sum * (1.f/64.f);
    float rstd = rsqrtf(sq * (1.f/64.f) - mean*mean + 1e-5f);
    __syncthreads();       // s_c ready

    #pragma unroll
    for (int q = 0; q < 8; q++) {
        float vals[4] = {vv[q].x,vv[q].y,vv[q].z,vv[q].w};
        #pragma unroll
        for (int j = 0; j < 4; j++) {
            int c = g*32 + q*4 + j;
            s_xT[c*128 + r] = (vals[j]-mean)*rstd*s_c[c] + s_c[64+c];
        }
    }
    __syncthreads();       // s_xT + s_w(wq) ready

    const int rg = tid & 31, cg = tid >> 5;
    const int r0 = rg*4, c0 = cg*8;

    // ---- pass Q ----
    {
        uint64_t acc[4][4];
        #pragma unroll
        for (int j = 0; j < 4; j++) { uint64_t b = pack2(s_c[128+c0+2*j], s_c[128+c0+2*j+1]);
            #pragma unroll
            for (int i = 0; i < 4; i++) acc[i][j] = b; }
        gemm_48p<64,128,64>(s_xT, s_w, r0, c0, acc);
        #pragma unroll
        for (int i = 0; i < 4; i++) {
            int nn = t0 + r0 + i;
            float o[8];
            unpack2(acc[i][0], o[0], o[1]);
            unpack2(acc[i][1], o[2], o[3]);
            unpack2(acc[i][2], o[4], o[5]);
            unpack2(acc[i][3], o[6], o[7]);
            float4 o0 = make_float4(phi_f(o[0]),phi_f(o[1]),phi_f(o[2]),phi_f(o[3]));
            float4 o1 = make_float4(phi_f(o[4]),phi_f(o[5]),phi_f(o[6]),phi_f(o[7]));
            *(float4*)(g_pq + (size_t)nn*DM + c0)     = o0;
            *(float4*)(g_pq + (size_t)nn*DM + c0 + 4) = o1;
        }
    }
    __syncthreads();
    for (int i = tid; i < 64*64; i += 256) s_w[i] = wk[i];
    __syncthreads();

    // ---- pass K ----
    {
        uint64_t acc[4][4];
        #pragma unroll
        for (int j = 0; j < 4; j++) { uint64_t b = pack2(s_c[192+c0+2*j], s_c[192+c0+2*j+1]);
            #pragma unroll
            for (int i = 0; i < 4; i++) acc[i][j] = b; }
        gemm_48p<64,128,64>(s_xT, s_w, r0, c0, acc);
        #pragma unroll
        for (int i = 0; i < 4; i++) {
            int nn = t0 + r0 + i;
            float mm = mask[nn];
            float o[8];
            unpack2(acc[i][0], o[0], o[1]);
            unpack2(acc[i][1], o[2], o[3]);
            unpack2(acc[i][2], o[4], o[5]);
            unpack2(acc[i][3], o[6], o[7]);
            float4 o0 = make_float4(phi_f(o[0])*mm,phi_f(o[1])*mm,phi_f(o[2])*mm,phi_f(o[3])*mm);
            float4 o1 = make_float4(phi_f(o[4])*mm,phi_f(o[5])*mm,phi_f(o[6])*mm,phi_f(o[7])*mm);
            *(float4*)(g_pk + (size_t)nn*DM + c0)     = o0;
            *(float4*)(g_pk + (size_t)nn*DM + c0 + 4) = o1;
        }
    }
    __syncthreads();
    for (int i = tid; i < 64*64; i += 256) s_w[i] = wv[i];
    __syncthreads();

    // ---- pass V ----
    {
        uint64_t acc[4][4];
        #pragma unroll
        for (int j = 0; j < 4; j++) { uint64_t b = pack2(s_c[256+c0+2*j], s_c[256+c0+2*j+1]);
            #pragma unroll
            for (int i = 0; i < 4; i++) acc[i][j] = b; }
        gemm_48p<64,128,64>(s_xT, s_w, r0, c0, acc);
        #pragma unroll
        for (int i = 0; i < 4; i++) {
            int nn = t0 + r0 + i;
            float o[8];
            unpack2(acc[i][0], o[0], o[1]);
            unpack2(acc[i][1], o[2], o[3]);
            unpack2(acc[i][2], o[4], o[5]);
            unpack2(acc[i][3], o[6], o[7]);
            *(float4*)(g_v + (size_t)nn*DM + c0)     = make_float4(o[0],o[1],o[2],o[3]);
            *(float4*)(g_v + (size_t)nn*DM + c0 + 4) = make_float4(o[4],o[5],o[6],o[7]);
        }
    }
}

// ================= Kernel 2: kv-state reduction (deterministic) =================
__global__ __launch_bounds__(256) void k_kvred() {
    __shared__ float s_red[8][72];
    int bh = blockIdx.x / SPLIT, chunk = blockIdx.x % SPLIT;
    int b = bh >> 3, h = bh & 7;
    int tid = threadIdx.x, wid = tid >> 5, lane = tid & 31;
    float kv[8][8] = {}; float ks[8] = {};
    int s0 = chunk * (SS / SPLIT);
    for (int s = s0 + tid; s < s0 + SS/SPLIT; s += 256) {
        int base = (b*SS + s)*DM + h*8;
        float4 p0 = *(const float4*)(g_pk + base), p1 = *(const float4*)(g_pk + base + 4);
        float4 v0 = *(const float4*)(g_v  + base), v1 = *(const float4*)(g_v  + base + 4);
        float pk[8] = {p0.x,p0.y,p0.z,p0.w,p1.x,p1.y,p1.z,p1.w};
        float vvv[8] = {v0.x,v0.y,v0.z,v0.w,v1.x,v1.y,v1.z,v1.w};
        #pragma unroll
        for (int d = 0; d < 8; d++) {
            ks[d] += pk[d];
            #pragma unroll
            for (int e = 0; e < 8; e++) kv[d][e] += pk[d]*vvv[e];
        }
    }
    #pragma unroll
    for (int o = 16; o > 0; o >>= 1) {
        #pragma unroll
        for (int d = 0; d < 8; d++) {
            ks[d] += __shfl_down_sync(0xffffffffu, ks[d], o);
            #pragma unroll
            for (int e = 0; e < 8; e++)
                kv[d][e] += __shfl_down_sync(0xffffffffu, kv[d][e], o);
        }
    }
    if (lane == 0) {
        #pragma unroll
        for (int d = 0; d < 8; d++) {
            #pragma unroll
            for (int e = 0; e < 8; e++) s_red[wid][d*8+e] = kv[d][e];
            s_red[wid][64+d] = ks[d];
        }
    }
    __syncthreads();
    if (tid < 72) {
        float acc = 0.f;
        #pragma unroll
        for (int w = 0; w < 8; w++) acc += s_red[w][tid];
        g_kvp[(size_t)blockIdx.x*72 + tid] = acc;
    }
}

// ================= Kernel 3: kv-combine + attention readout + @wo + residual =================
// 128 tokens/block; attention readout in two head-passes to cut live registers
__global__ __launch_bounds__(256) void k_att(
    const float* __restrict__ wo, const float* __restrict__ bo)
{
    extern __shared__ float sm[];
    float* s_attT = sm;               // [64][128]
    float* s_w    = sm + 64*128;      // wo [64][64]
    float* s_kv   = s_w + 64*64;      // 512
    float* s_ks   = s_kv + 512;       // 64
    float* s_bo   = s_ks + 64;        // 64
    const int tid = threadIdx.x;
    const int t0 = blockIdx.x * 128;
    const int b = t0 >> 12;           // t0 / SS

    for (int i = tid; i < 64*64; i += 256) s_w[i] = wo[i];
    // fused kv-combine
    for (int i = tid; i < NH*72; i += 256) {
        int h = i / 72, idx = i % 72;
        float acc = 0.f;
        #pragma unroll
        for (int c = 0; c < SPLIT; c++)
            acc += g_kvp[(size_t)((b*NH + h)*SPLIT + c)*72 + idx];
        if (idx < 64) s_kv[h*64 + idx] = acc;
        else          s_ks[h*8 + idx - 64] = acc;
    }
    if (tid < 64) s_bo[tid] = bo[tid];
    __syncthreads();

    const int r = tid >> 1, g = tid & 1;
    const int n = t0 + r;

    // two passes of 2 heads each: only 16 pq values live at a time
    #pragma unroll
    for (int half = 0; half < 2; half++) {
        float p[16];
        {
            const float4* src = (const float4*)(g_pq + (size_t)n*DM + g*32 + half*16);
            #pragma unroll
            for (int q = 0; q < 4; q++) {
                float4 v = src[q];
                p[q*4+0]=v.x; p[q*4+1]=v.y; p[q*4+2]=v.z; p[q*4+3]=v.w;
            }
        }
        #pragma unroll
        for (int u = 0; u < 2; u++) {
            int h = g*4 + half*2 + u;
            float den = 0.f;
            #pragma unroll
            for (int d = 0; d < 8; d++) den += p[u*8+d] * s_ks[h*8+d];
            float inv = 1.f / (den + 1e-6f);
            const float* kvb = s_kv + h*64;
            #pragma unroll
            for (int e = 0; e < 8; e++) {
                float num = 0.f;
                #pragma unroll
                for (int d = 0; d < 8; d++) num += p[u*8+d] * kvb[d*8+e];
                s_attT[(h*8 + e)*128 + r] = num * inv;
            }
        }
    }
    __syncthreads();

    {
        int rg = tid & 31, cg = tid >> 5;
        int r0 = rg*4, c0 = cg*8;
        uint64_t acc[4][4];
        #pragma unroll
        for (int j = 0; j < 4; j++) { uint64_t bb = pack2(s_bo[c0+2*j], s_bo[c0+2*j+1]);
            #pragma unroll
            for (int i = 0; i < 4; i++) acc[i][j] = bb; }
        gemm_48p<64,128,64>(s_attT, s_w, r0, c0, acc);
        #pragma unroll
        for (int i = 0; i < 4; i++) {
            float o[8];
            unpack2(acc[i][0], o[0], o[1]);
            unpack2(acc[i][1], o[2], o[3]);
            unpack2(acc[i][2], o[4], o[5]);
            unpack2(acc[i][3], o[6], o[7]);
            float4* ph = (float4*)(g_hh + (size_t)(t0+r0+i)*DM + c0);
            float4 h0 = ph[0], h1 = ph[1];
            h0.x += o[0]; h0.y += o[1]; h0.z += o[2]; h0.w += o[3];
            h1.x += o[4]; h1.y += o[5]; h1.z += o[6]; h1.w += o[7];
            ph[0] = h0; ph[1] = h1;
        }
    }
}

// ================= Kernel 4: fused LN2 + FFN chunked (up,gelu,down-accum) + residual =================
// 64 tokens/block; FF dim in 4 chunks of 64; down accumulates in registers.
// smem ~50 KB -> 4 blocks/SM (50% occ)
__global__ __launch_bounds__(256, 4) void k_ffn(
    const float* __restrict__ ls, const float* __restrict__ lb,
    const float* __restrict__ w1, const float* __restrict__ b1,
    const float* __restrict__ w2, const float* __restrict__ b2)
{
    extern __shared__ float sm[];
    float* s_yT  = sm;                 // [64k][64t]
    float* s_t1c = sm + 64*64;         // [64ff][64t] chunk
    float* s_w   = sm + 2*64*64;       // [64][64] staging (w1 chunk / w2 chunk)
    float* s_c   = s_w + 64*64;        // ls 64 | lb 64 | b1 256 | b2 64 = 448
    const int tid = threadIdx.x;
    const int t0 = blockIdx.x * 64;
    const int rg = tid & 15, cg = tid >> 4;
    const int r0 = rg*4, c0 = cg*4;

    for (int i = tid; i < 448; i += 256) {
        float v;
        if      (i < 64)  v = ls[i];
        else if (i < 128) v = lb[i-64];
        else if (i < 384) v = b1[i-128];
        else              v = b2[i-384];
        s_c[i] = v;
    }

    // LN2 in registers (4 threads / row, 16 cols each)
    const int r = tid >> 2, g = tid & 3;
    const int n = t0 + r;
    float4 vv[4];
    {
        const float4* src = (const float4*)(g_hh + (size_t)n*DM + g*16);
        #pragma unroll
        for (int q = 0; q < 4; q++) vv[q] = src[q];
    }
    float sum = 0.f, sq = 0.f;
    #pragma unroll
    for (int q = 0; q < 4; q++) {
        sum += vv[q].x+vv[q].y+vv[q].z+vv[q].w;
        sq  += vv[q].x*vv[q].x+vv[q].y*vv[q].y+vv[q].z*vv[q].z+vv[q].w*vv[q].w;
    }
    sum += __shfl_xor_sync(0xffffffffu, sum, 1);
    sq  += __shfl_xor_sync(0xffffffffu, sq , 1);
    sum += __shfl_xor_sync(0xffffffffu, sum, 2);
    sq  += __shfl_xor_sync(0xffffffffu, sq , 2);
    float mean = sum * (1.f/64.f);
    float rstd = rsqrtf(sq * (1.f/64.f) - mean*mean + 1e-5f);
    __syncthreads();   // s_c staged

    #pragma unroll
    for (int q = 0; q < 4; q++) {
        float vals[4] = {vv[q].x,vv[q].y,vv[q].z,vv[q].w};
        #pragma unroll
        for (int j = 0; j < 4; j++) {
            int c = g*16 + q*4 + j;
            s_yT[c*64 + r] = (vals[j]-mean)*rstd*s_c[c] + s_c[64+c];
        }
    }

    // persistent down accumulator (tokens r0.., dm cols c0..)
    uint64_t accD[4][2];
    #pragma unroll
    for (int j = 0; j < 2; j++) { uint64_t bb = pack2(s_c[384+c0+2*j], s_c[384+c0+2*j+1]);
        #pragma unroll
        for (int i = 0; i < 4; i++) accD[i][j] = bb; }

    for (int c = 0; c < 4; c++) {
        __syncthreads();   // yT ready (iter 0) / prior s_w + t1c reads done
        for (int i = tid; i < 4096; i += 256) {
            int k = i >> 6, j = i & 63;
            s_w[i] = w1[k*FFD + c*64 + j];
        }
        __syncthreads();
        // up chunk GEMM (4x4 tiles, 64 tok x 64 ff)
        uint64_t accU[4][2];
        #pragma unroll
        for (int j = 0; j < 2; j++) { uint64_t bb = pack2(s_c[128 + c*64 + c0+2*j], s_c[128 + c*64 + c0+2*j+1]);
            #pragma unroll
            for (int i = 0; i < 4; i++) accU[i][j] = bb; }
        gemm_44p<64,64,64>(s_yT, s_w, r0, c0, accU);
        #pragma unroll
        for (int i = 0; i < 4; i++) {
            float o0,o1,o2,o3;
            unpack2(accU[i][0], o0, o1);
            unpack2(accU[i][1], o2, o3);
            s_t1c[(c0+0)*64 + r0+i] = gelu_f(o0);
            s_t1c[(c0+1)*64 + r0+i] = gelu_f(o1);
            s_t1c[(c0+2)*64 + r0+i] = gelu_f(o2);
            s_t1c[(c0+3)*64 + r0+i] = gelu_f(o3);
        }
        __syncthreads();   // t1c written; s_w free for restage
        for (int i = tid; i < 4096; i += 256) {
            int k = i >> 6, j = i & 63;
            s_w[i] = w2[(size_t)(c*64 + k)*DM + j];
        }
        __syncthreads();
        gemm_44p<64,64,64>(s_t1c, s_w, r0, c0, accD);
    }

    // epilogue: hh += accD (bias already folded)
    #pragma unroll
    for (int i = 0; i < 4; i++) {
        float o0,o1,o2,o3;
        unpack2(accD[i][0], o0, o1);
        unpack2(accD[i][1], o2, o3);
        float4* ph = (float4*)(g_hh + (size_t)(t0+r0+i)*DM + c0);
        float4 h0 = *ph;
        h0.x += o0; h0.y += o1; h0.z += o2; h0.w += o3;
        *ph = h0;
    }
}

// ================= Kernel 5: final LN + mask + output GEMM =================
// 128 tokens/block x 64-col chunks -> smem ~49 KB -> 4 blocks/SM
__global__ __launch_bounds__(256, 4) void k_out(
    const float* __restrict__ mask,
    const float* __restrict__ ls, const float* __restrict__ lb,
    const float* __restrict__ w_out, const float* __restrict__ b_out,
    float* __restrict__ out)
{
    extern __shared__ float sm[];
    float* s_xT = sm;               // [64][128]
    float* s_w  = sm + 64*128;      // [64][64] chunk
    float* s_c  = s_w + 64*64;      // ls 64 | lb 64 | bias 64
    const int tid = threadIdx.x;
    const int t0 = blockIdx.x * 128;
    const int c00 = blockIdx.y * 64;

    for (int i = tid; i < 192; i += 256) {
        float v;
        if      (i < 64)  v = ls[i];
        else if (i < 128) v = lb[i-64];
        else { int c = c00 + i - 128; v = (c < CC) ? b_out[c] : 0.f; }
        s_c[i] = v;
    }
    for (int i = tid; i < 64*64; i += 256) {
        int k = i >> 6, j = i & 63;
        int c = c00 + j;
        s_w[i] = (c < CC) ? w_out[(size_t)k*CC + c] : 0.f;
    }

    // final LN (+mask) in registers (2 threads / row, 32 cols each)
    const int r = tid >> 1, g = tid & 1;
    const int n = t0 + r;
    float4 vv[8];
    {
        const float4* src = (const float4*)(g_hh + (size_t)n*DM + g*32);
        #pragma unroll
        for (int q = 0; q < 8; q++) vv[q] = src[q];
    }
    float sum = 0.f, sq = 0.f;
    #pragma unroll
    for (int q = 0; q < 8; q++) {
        sum += vv[q].x+vv[q].y+vv[q].z+vv[q].w;
        sq  += vv[q].x*vv[q].x+vv[q].y*vv[q].y+vv[q].z*vv[q].z+vv[q].w*vv[q].w;
    }
    sum += __shfl_xor_sync(0xffffffffu, sum, 1);
    sq  += __shfl_xor_sync(0xffffffffu, sq , 1);
    float mean = sum * (1.f/64.f);
    float rstd = rsqrtf(sq * (1.f/64.f) - mean*mean + 1e-5f);
    float m = mask[n];
    __syncthreads();

    #pragma unroll
    for (int q = 0; q < 8; q++) {
        float vals[4] = {vv[q].x,vv[q].y,vv[q].z,vv[q].w};
        #pragma unroll
        for (int j = 0; j < 4; j++) {
            int c = g*32 + q*4 + j;
            s_xT[c*128 + r] = ((vals[j]-mean)*rstd*s_c[c] + s_c[64+c]) * m;
        }
    }
    __syncthreads();

    // GEMM: 128 tok x 64 cols = 256 tiles (4x8), 1/thread
    {
        int rg = tid & 31, cg = tid >> 5;
        int r0 = rg*4, c0 = cg*8;
        uint64_t acc[4][4];
        #pragma unroll
        for (int j = 0; j < 4; j++) { uint64_t bb = pack2(s_c[128+c0+2*j], s_c[128+c0+2*j+1]);
            #pragma unroll
            for (int i = 0; i < 4; i++) acc[i][j] = bb; }
        gemm_48p<64,128,64>(s_xT, s_w, r0, c0, acc);
        #pragma unroll
        for (int i = 0; i < 4; i++) {
            float o[8];
            unpack2(acc[i][0], o[0], o[1]);
            unpack2(acc[i][1], o[2], o[3]);
            unpack2(acc[i][2], o[4], o[5]);
            unpack2(acc[i][3], o[6], o[7]);
            size_t ob = (size_t)(t0+r0+i)*CC + c00 + c0;
            #pragma unroll
            for (int j = 0; j < 8; j++)
                if (c00 + c0 + j < CC) out[ob + j] = o[j];
        }
    }
}

extern "C" void kernel_launch(void* const* d_in, const int* in_sizes, int n_in,
                              void* d_out, int out_size) {
    const float* ex    = (const float*)d_in[0];
    const int*   labels= (const int*)  d_in[1];
    const float* mask  = (const float*)d_in[2];
    const float* we    = (const float*)d_in[3];
    const float* be    = (const float*)d_in[4];
    const float* lemb  = (const float*)d_in[5];
    const float* w_in  = (const float*)d_in[6];
    const float* b_in  = (const float*)d_in[7];
    const float* ln1_s = (const float*)d_in[8];
    const float* ln1_b = (const float*)d_in[9];
    const float* wq    = (const float*)d_in[10];
    const float* bq    = (const float*)d_in[11];
    const float* wk    = (const float*)d_in[12];
    const float* bk    = (const float*)d_in[13];
    const float* wv    = (const float*)d_in[14];
    const float* bv    = (const float*)d_in[15];
    const float* wo    = (const float*)d_in[16];
    const float* bo    = (const float*)d_in[17];
    const float* ln2_s = (const float*)d_in[18];
    const float* ln2_b = (const float*)d_in[19];
    const float* w1    = (const float*)d_in[20];
    const float* b1    = (const float*)d_in[21];
    const float* w2    = (const float*)d_in[22];
    const float* b2    = (const float*)d_in[23];
    const float* lnf_s = (const float*)d_in[24];
    const float* lnf_b = (const float*)d_in[25];
    const float* w_out = (const float*)d_in[26];
    const float* b_out = (const float*)d_in[27];
    float* out = (float*)d_out;

    const int smem_embed = (2*128*68 + 128*64 + 192) * 4;
    const int smem_qkv   = (64*128 + 64*64 + 320) * 4;
    const int smem_att   = (64*128 + 64*64 + 512 + 64 + 64) * 4;
    const int smem_ffn   = (3*64*64 + 448) * 4;
    const int smem_out   = (64*128 + 64*64 + 192) * 4;

    cudaFuncSetAttribute(k_embed, cudaFuncAttributeMaxDynamicSharedMemorySize, smem_embed);
    cudaFuncSetAttribute(k_qkv,   cudaFuncAttributeMaxDynamicSharedMemorySize, smem_qkv);
    cudaFuncSetAttribute(k_att,   cudaFuncAttributeMaxDynamicSharedMemorySize, smem_att);
    cudaFuncSetAttribute(k_ffn,   cudaFuncAttributeMaxDynamicSharedMemorySize, smem_ffn);
    cudaFuncSetAttribute(k_out,   cudaFuncAttributeMaxDynamicSharedMemorySize, smem_out);

    k_embed<<<NTOK/64, 256, smem_embed>>>(ex, labels, we, be, lemb, w_in, b_in);
    for (int i = 0; i < NL; i++) {
        k_qkv<<<NTOK/128, 256, smem_qkv>>>(mask, ln1_s + i*DM, ln1_b + i*DM,
                                wq + i*DM*DM, bq + i*DM,
                                wk + i*DM*DM, bk + i*DM,
                                wv + i*DM*DM, bv + i*DM);
        k_kvred<<<NB*NH*SPLIT, 256>>>();
        k_att<<<NTOK/128, 256, smem_att>>>(wo + i*DM*DM, bo + i*DM);
        k_ffn<<<NTOK/64, 256, smem_ffn>>>(ln2_s + i*DM, ln2_b + i*DM,
                                 w1 + i*DM*FFD, b1 + i*FFD,
                                 w2 + i*FFD*DM, b2 + i*DM);
    }
    dim3 og(NTOK/128, (CC + 63)/64);
    k_out<<<og, 256, smem_out>>>(mask, lnf_s, lnf_b, w_out, b_out, out);
}